// round 17
// baseline (speedup 1.0000x reference)
#include <cuda_runtime.h>
#include <math.h>

// ---------------------------------------------------------------------------
// HierarchicalCNN: two 3-layer strided conv1d nets + pooled heads + routing.
// Both conv stages on tf32 mma.sync m16n8k8 (single pass, rna).
//
// R17: full producer-side chain. conv0 runs as its own kernel, storing a0
// parity-split / tf32-rounded / ci-interleaved (g_a0e, g_a0o). conv01's B
// staging is then pure cp.async (like conv2's since R16). conv01 stores a1
// in conv2's B format (g_ae, g_ao). All halo rows are never written and
// stay zero from static initialization.
//
// Smem tiles: packed pitch-16 with seg-XOR swizzle:
//   float offset f in row -> ((f>>2) ^ (row&3))<<2 | (f&3)
// Column interleave pos(ci) = (ci>>3)*8 + (ci&3)*2 + ((ci>>2)&1).
// tap -> (parity, row offset): k0:(odd,0) k1:(even,0) k2:(odd,1)
//                              k3:(even,1) k4:(odd,2)
// Mainloops: 128co x 128t CTA tiles, 2 CTAs/SM, stage -> sync -> mma -> sync.
// ---------------------------------------------------------------------------

typedef unsigned int       u32;
typedef unsigned long long ull;

#define A0_ROWS 1026
__device__ float g_a0e[512][A0_ROWS][64];   // a0[2r],   tf32, interleaved
__device__ float g_a0o[512][A0_ROWS][64];   // a0[2r-1], tf32, interleaved
#define AE_ROWS 514
__device__ float g_ae[512][AE_ROWS][128];   // a1[2r],   tf32, interleaved
__device__ float g_ao[512][AE_ROWS][128];   // a1[2r-1], tf32, interleaved
__device__ float g_feat[2][512][256];
// tf32 conv1 weights, interleaved cols: [net][chunk 4][tap 5][co 128][pos 16]
__device__ __align__(16) float g_w1tf[2][4][5][128][16];
// tf32 conv2 weights: [net][coh 2][chunk 8][tap 5][co 128][pos 16]
__device__ __align__(16) float g_w2tf[2][2][8][5][128][16];

// ---------------- helpers ---------------------------------------------------
__device__ __forceinline__ u32 to_tf32(float v) {
    u32 r;
    asm("cvt.rna.tf32.f32 %0, %1;" : "=r"(r) : "f"(v));
    return r;
}
__device__ __forceinline__ void mma_tf32(float* d, const u32* a, u32 b0, u32 b1) {
    asm volatile(
        "mma.sync.aligned.m16n8k8.row.col.f32.tf32.tf32.f32 "
        "{%0,%1,%2,%3}, {%4,%5,%6,%7}, {%8,%9}, {%0,%1,%2,%3};"
        : "+f"(d[0]), "+f"(d[1]), "+f"(d[2]), "+f"(d[3])
        : "r"(a[0]), "r"(a[1]), "r"(a[2]), "r"(a[3]), "r"(b0), "r"(b1));
}
__device__ __forceinline__ void fma2(ull& d, ull a, ull b) {
    asm("fma.rn.f32x2 %0, %1, %2, %0;" : "+l"(d) : "l"(a), "l"(b));
}
__device__ __forceinline__ ull pack2(float lo, float hi) {
    ull r;
    asm("mov.b64 %0, {%1, %2};" : "=l"(r) : "f"(lo), "f"(hi));
    return r;
}
__device__ __forceinline__ void unpack2(ull v, float& lo, float& hi) {
    asm("mov.b64 {%0, %1}, %2;" : "=f"(lo), "=f"(hi) : "l"(v));
}
__device__ __forceinline__ u32 smem_u32(const void* p) {
    u32 a;
    asm("{ .reg .u64 t; cvta.to.shared.u64 t, %1; cvt.u32.u64 %0, t; }"
        : "=r"(a) : "l"(p));
    return a;
}
__device__ __forceinline__ void cp16(u32 dst, const void* src) {
    asm volatile("cp.async.cg.shared.global [%0], [%1], 16;" :: "r"(dst), "l"(src));
}
#define CP_COMMIT() asm volatile("cp.async.commit_group;" ::: "memory")
#define CP_WAIT0()  asm volatile("cp.async.wait_group 0;" ::: "memory")

__host__ __device__ constexpr int posi(int ci) {
    return ((ci >> 3) << 3) + ((ci & 3) << 1) + ((ci >> 2) & 1);
}
__device__ __forceinline__ int swzf(int f, int s) {
    return ((((f >> 2) ^ s) << 2) | (f & 3));
}

#define A_FLTS (5 * 128 * 16)   // 10240
#define B_ROWS 132
#define B_FLTS (B_ROWS * 16)    // 2112

// ---------------------------------------------------------------------------
// prep kernels (packed [co][pos 16] tiles; swizzle applied at staging time)
// ---------------------------------------------------------------------------
__global__ __launch_bounds__(256)
void prep_w1_kernel(const float* __restrict__ w_n0, const float* __restrict__ w_n1)
{
    int idx = blockIdx.x * 256 + threadIdx.x;
    const int total = 2 * 4 * 5 * 128 * 16;
    if (idx >= total) return;
    int r = idx;
    int ci = r & 15;   r >>= 4;
    int co = r & 127;  r >>= 7;
    int tap = r % 5;   r /= 5;
    int chunk = r & 3; r >>= 2;
    int net = r;
    const float* w = net ? w_n1 : w_n0;
    float v = w[(size_t)co * 320 + (chunk * 16 + ci) * 5 + tap];
    g_w1tf[net][chunk][tap][co][posi(ci)] = __uint_as_float(to_tf32(v));
}

__global__ __launch_bounds__(256)
void prep_w2_kernel(const float* __restrict__ w_n0, const float* __restrict__ w_n1)
{
    int idx = blockIdx.x * 256 + threadIdx.x;
    const int total = 2 * 2 * 8 * 5 * 128 * 16;
    if (idx >= total) return;
    int r = idx;
    int ci = r & 15;   r >>= 4;
    int co = r & 127;  r >>= 7;
    int tap = r % 5;   r /= 5;
    int chunk = r & 7; r >>= 3;
    int coh = r & 1;   r >>= 1;
    int net = r;
    const float* w = net ? w_n1 : w_n0;
    float v = w[(size_t)(coh * 128 + co) * 640 + (chunk * 16 + ci) * 5 + tap];
    g_w2tf[net][coh][chunk][tap][co][posi(ci)] = __uint_as_float(to_tf32(v));
}

// ---------------------------------------------------------------------------
// conv0: x -> a0 (relu, tf32, parity-split, ci-interleaved rows of 64).
// grid (512 b, 32 t-groups), 256 threads; each block does 64 tmid rows.
// Thread (rl = tid>>2, q = tid&3): computes ci block q (16 ci = 8 fma2
// groups) of row tmid = t0 + rl into smem buf, then cooperative coalesced
// row copies to g_a0e/g_a0o by parity.
// ---------------------------------------------------------------------------
__global__ __launch_bounds__(256)
void conv0_kernel(const float* __restrict__ x,
                  const float* __restrict__ w0,  // [64,2,5]
                  const float* __restrict__ b0)  // [64]
{
    __shared__ ull   w0d[320];      // [gg 32][k 10] pairs (ci, ci+4)
    __shared__ ull   b0d[32];
    __shared__ float buf[64][64];

    const int tid = threadIdx.x;
    const int b   = blockIdx.x;
    const int t0  = blockIdx.y * 64;

    for (int i = tid; i < 320; i += 256) {
        int k = i % 10, gg = i / 10;
        int ci = (gg >> 3) * 16 + ((gg & 7) & 3) + (((gg & 7) >> 2) << 3);
        w0d[i] = pack2(w0[ci * 10 + k], w0[(ci + 4) * 10 + k]);
    }
    if (tid < 32) {
        int gg = tid;
        int ci = (gg >> 3) * 16 + ((gg & 7) & 3) + (((gg & 7) >> 2) << 3);
        b0d[tid] = pack2(b0[ci], b0[ci + 4]);
    }
    __syncthreads();

    const int rl = tid >> 2;
    const int q  = tid & 3;
    const int tmid = t0 + rl;
    const float* xb = x + (size_t)b * 2 * 4096;

    ull xp[10];
#pragma unroll
    for (int k = 0; k < 5; k++) {
        int gx = 2 * tmid - 1 + k;
        bool ok = (gx >= 0 && gx < 4096);
        float v0 = ok ? xb[gx] : 0.0f;
        float v1 = ok ? xb[4096 + gx] : 0.0f;
        xp[k]     = pack2(v0, v0);
        xp[5 + k] = pack2(v1, v1);
    }

#pragma unroll
    for (int g = 0; g < 8; g++) {
        int gg = q * 8 + g;
        ull a2 = b0d[gg];
        const ull* wg = &w0d[gg * 10];
#pragma unroll
        for (int k = 0; k < 10; k++) fma2(a2, wg[k], xp[k]);
        float lo, hi;
        unpack2(a2, lo, hi);
        buf[rl][q * 16 + 2 * g]     = __uint_as_float(to_tf32(fmaxf(lo, 0.0f)));
        buf[rl][q * 16 + 2 * g + 1] = __uint_as_float(to_tf32(fmaxf(hi, 0.0f)));
    }
    __syncthreads();

    // coalesced row copies by parity: even tmid -> a0e[tm/2], odd -> a0o[(tm+1)/2]
    for (int i = tid; i < 64 * 16; i += 256) {
        int r = i >> 4, seg = i & 15;
        int tm = t0 + r;
        float* dst = (tm & 1) ? &g_a0o[b][(tm + 1) >> 1][0]
                              : &g_a0e[b][tm >> 1][0];
        *(float4*)&dst[seg * 4] = *(float4*)&buf[r][seg * 4];
    }
}

// ---------------------------------------------------------------------------
// A stage: cp.async packed [640 rows][16] -> swizzled pitch-16 smem tile
// ---------------------------------------------------------------------------
#define STAGE_A(uAs, srcp)                                                     \
    {                                                                          \
        const char* _src = (const char*)(srcp);                                \
        _Pragma("unroll")                                                      \
        for (int r = 0; r < 10; r++) {                                         \
            int i = r * 256 + tid;                                             \
            int row = i >> 2, seg = i & 3;                                     \
            int off = (row << 4) + (((seg ^ (row & 3)) << 2));                 \
            cp16((uAs) + (u32)off * 4, _src + (size_t)i * 16);                 \
        }                                                                      \
    }

// B stage: cp.async rows (64B = 4 segs) from parity arrays into swizzled
// Be (rows 0..128) / Bo (rows 0..129) tiles.
#define STAGE_B(uBe, uBo, srcE, srcO, rowpitch)                                \
    for (int i = tid; i < 1036; i += 256) {                                    \
        int rr = i >> 2, seg = i & 3;                                          \
        if (rr < 129) {                                                        \
            cp16((uBe) + (u32)(rr * 16 + ((seg ^ (rr & 3)) << 2)) * 4,         \
                 (const char*)(srcE) + (size_t)rr * (rowpitch) + seg * 16);    \
        } else {                                                               \
            int mm = rr - 129;                                                 \
            cp16((uBo) + (u32)(mm * 16 + ((seg ^ (mm & 3)) << 2)) * 4,         \
                 (const char*)(srcO) + (size_t)mm * (rowpitch) + seg * 16);    \
        }                                                                      \
    }

// ---------------------------------------------------------------------------
// MMA over one staged chunk (5 taps), warp tile 32co x 64t (j = 0..7).
// ---------------------------------------------------------------------------
#define MMA_CHUNK(As, BeT, BoT)                                                \
    {                                                                          \
        const int sA = lr & 3;                                                 \
        const int offA0 = swzf(2 * lc, sA);                                    \
        const int offA1 = swzf(2 * lc + 8, sA);                                \
        _Pragma("unroll")                                                      \
        for (int tap = 0; tap < 5; tap++) {                                    \
            const float* Bb = (tap == 1 || tap == 3) ? (BeT) : (BoT);          \
            const int roff = (tap < 2) ? 0 : ((tap == 4) ? 2 : 1);             \
            const int sB = (lr + roff) & 3;                                    \
            const int offB0 = swzf(2 * lc, sB);                                \
            const int offB1 = swzf(2 * lc + 8, sB);                            \
            u32 a[2][2][4];                                                    \
            _Pragma("unroll")                                                  \
            for (int m = 0; m < 2; m++) {                                      \
                const float* ab = (As) + (tap * 128 + wco + m * 16 + lr) * 16; \
                _Pragma("unroll")                                              \
                for (int h = 0; h < 2; h++) {                                  \
                    int oa = h ? offA1 : offA0;                                \
                    float2 q0 = *(const float2*)&ab[oa];                       \
                    float2 q1 = *(const float2*)&ab[128 + oa];                 \
                    a[m][h][0] = __float_as_uint(q0.x);                        \
                    a[m][h][1] = __float_as_uint(q1.x);                        \
                    a[m][h][2] = __float_as_uint(q0.y);                        \
                    a[m][h][3] = __float_as_uint(q1.y);                        \
                }                                                              \
            }                                                                  \
            const float* bb = Bb + (wt + lr + roff) * 16;                      \
            _Pragma("unroll")                                                  \
            for (int h = 0; h < 2; h++) {                                      \
                int ob = h ? offB1 : offB0;                                    \
                _Pragma("unroll")                                              \
                for (int j = 0; j < 8; j++) {                                  \
                    float2 p = *(const float2*)&bb[j * 128 + ob];              \
                    u32 pb0 = __float_as_uint(p.x);                            \
                    u32 pb1 = __float_as_uint(p.y);                            \
                    mma_tf32(acc[0][j], a[0][h], pb0, pb1);                    \
                    mma_tf32(acc[1][j], a[1][h], pb0, pb1);                    \
                }                                                              \
            }                                                                  \
        }                                                                      \
    }

// ---------------------------------------------------------------------------
// conv01: conv1 tf32 mma, B staged by cp.async from g_a0e/g_a0o.
// Output -> g_ae/g_ao in conv2-ready format.
// grid (512 b, 8 t-tiles), 256 threads. CTA 128co x 128t.
// smem floats: As[10240] | Be[2112] | Bo[2112]
// ---------------------------------------------------------------------------
#define O1_BE  A_FLTS
#define O1_BO  (O1_BE + B_FLTS)
#define C1_SMEM ((O1_BO + B_FLTS) * 4)   // 57,856 bytes -> 2 CTAs/SM

__global__ __launch_bounds__(256, 2)
void conv01_mma_kernel(const float* __restrict__ b1,  // [128]
                       int net)
{
    extern __shared__ float sm[];
    float* As = sm;
    float* Be = sm + O1_BE;
    float* Bo = sm + O1_BO;

    const int tid  = threadIdx.x;
    const int lane = tid & 31;
    const int wid  = tid >> 5;
    const int b    = blockIdx.x;
    const int tt0  = blockIdx.y * 128;

    const int wco = (wid & 3) * 32;
    const int wt  = (wid >> 2) * 64;
    const int lr  = lane >> 2;
    const int lc  = lane & 3;
    const u32 uAs = smem_u32(As);
    const u32 uBe = smem_u32(Be);
    const u32 uBo = smem_u32(Bo);

    float acc[2][8][4];
#pragma unroll
    for (int m = 0; m < 2; m++)
#pragma unroll
        for (int j = 0; j < 8; j++)
#pragma unroll
            for (int e = 0; e < 4; e++) acc[m][j][e] = 0.0f;

    for (int chunk = 0; chunk < 4; chunk++) {
        STAGE_A(uAs, &g_w1tf[net][chunk][0][0][0]);
        STAGE_B(uBe, uBo,
                &g_a0e[b][tt0][chunk * 16], &g_a0o[b][tt0][chunk * 16],
                64 * 4)
        CP_COMMIT();
        CP_WAIT0();
        __syncthreads();

        MMA_CHUNK(As, Be, Bo)
        __syncthreads();
    }

    // ---- epilogue: bias+relu, tf32-round, write ae/ao (interleaved cols).
    //      co = wco+m*16+lr (+8), t = tt0 + wt + j*8 + 2lc (+1). ----
#pragma unroll
    for (int m = 0; m < 2; m++) {
        int co_a = wco + m * 16 + lr;
        int colA = wco + m * 16 + posi(lr);
        int colB = colA + 8;
        float bva = b1[co_a];
        float bvb = b1[co_a + 8];
#pragma unroll
        for (int j = 0; j < 8; j++) {
            int rE = (tt0 + wt + j * 8) / 2 + lc;
            g_ae[b][rE][colA] = __uint_as_float(
                to_tf32(fmaxf(acc[m][j][0] + bva, 0.0f)));
            g_ao[b][rE + 1][colA] = __uint_as_float(
                to_tf32(fmaxf(acc[m][j][1] + bva, 0.0f)));
            g_ae[b][rE][colB] = __uint_as_float(
                to_tf32(fmaxf(acc[m][j][2] + bvb, 0.0f)));
            g_ao[b][rE + 1][colB] = __uint_as_float(
                to_tf32(fmaxf(acc[m][j][3] + bvb, 0.0f)));
        }
    }
}

// ---------------------------------------------------------------------------
// conv2: tf32 warp-MMA + fused pool. B staged by cp.async from g_ae/g_ao.
// grid (512 b, 4 t-tiles, 2 co-halves), 256 threads. CTA 128co x 128t.
// smem floats: As[10240] | Be[2112] | Bo[2112]
// ---------------------------------------------------------------------------
#define O2_BE  A_FLTS
#define O2_BO  (O2_BE + B_FLTS)
#define C2_SMEM ((O2_BO + B_FLTS) * 4)   // 57,856 bytes -> 2 CTAs/SM

__global__ __launch_bounds__(256, 2)
void conv2_mma_kernel(const float* __restrict__ bias,  // [256]
                      float* __restrict__ feat,        // [512,256] sums
                      int net)
{
    extern __shared__ float sm[];
    float* As = sm;
    float* Be = sm + O2_BE;
    float* Bo = sm + O2_BO;

    const int tid  = threadIdx.x;
    const int lane = tid & 31;
    const int wid  = tid >> 5;
    const int b    = blockIdx.x;
    const int tt0  = blockIdx.y * 128;
    const int co0  = blockIdx.z * 128;

    const int wco = (wid & 3) * 32;
    const int wt  = (wid >> 2) * 64;
    const int lr  = lane >> 2;
    const int lc  = lane & 3;
    const u32 uAs = smem_u32(As);
    const u32 uBe = smem_u32(Be);
    const u32 uBo = smem_u32(Bo);

    float acc[2][8][4];
#pragma unroll
    for (int m = 0; m < 2; m++)
#pragma unroll
        for (int j = 0; j < 8; j++)
#pragma unroll
            for (int e = 0; e < 4; e++) acc[m][j][e] = 0.0f;

    for (int chunk = 0; chunk < 8; chunk++) {
        STAGE_A(uAs, &g_w2tf[net][co0 >> 7][chunk][0][0][0]);
        STAGE_B(uBe, uBo,
                &g_ae[b][tt0][chunk * 16], &g_ao[b][tt0][chunk * 16],
                128 * 4)
        CP_COMMIT();
        CP_WAIT0();
        __syncthreads();

        MMA_CHUNK(As, Be, Bo)
        __syncthreads();
    }

    // ---- epilogue: bias+relu, sum over t, quad-reduce, atomicAdd ----
    float* fb = feat + (size_t)b * 256;
#pragma unroll
    for (int m = 0; m < 2; m++) {
        int r0 = co0 + wco + m * 16 + lr;
        int r1 = r0 + 8;
        float bv0 = __ldg(&bias[r0]);
        float bv1 = __ldg(&bias[r1]);
        float s0 = 0.0f, s1 = 0.0f;
#pragma unroll
        for (int j = 0; j < 8; j++) {
            s0 += fmaxf(acc[m][j][0] + bv0, 0.0f) + fmaxf(acc[m][j][1] + bv0, 0.0f);
            s1 += fmaxf(acc[m][j][2] + bv1, 0.0f) + fmaxf(acc[m][j][3] + bv1, 0.0f);
        }
        s0 += __shfl_xor_sync(0xffffffffu, s0, 1);
        s0 += __shfl_xor_sync(0xffffffffu, s0, 2);
        s1 += __shfl_xor_sync(0xffffffffu, s1, 1);
        s1 += __shfl_xor_sync(0xffffffffu, s1, 2);
        if (lc == 0) {
            atomicAdd(&fb[r0], s0);
            atomicAdd(&fb[r1], s1);
        }
    }
}

// ---------------------------------------------------------------------------
__global__ void zero_feat_kernel()
{
    int i = blockIdx.x * 256 + threadIdx.x;
    if (i < 2 * 512 * 256) ((float*)g_feat)[i] = 0.0f;
}

// ---------------------------------------------------------------------------
// heads + softmax + hierarchical routing. 1 warp per sample.
// ---------------------------------------------------------------------------
__global__ __launch_bounds__(32)
void head_kernel(const float* __restrict__ wh1, const float* __restrict__ bh1,
                 const float* __restrict__ wh2, const float* __restrict__ bh2,
                 float* __restrict__ out)
{
    const int b = blockIdx.x;
    const int lane = threadIdx.x;
    const float* f1 = &g_feat[0][b][0];
    const float* f2 = &g_feat[1][b][0];
    const float inv_pool = 1.0f / 512.0f;

    float lg1[3], lg2[2];
#pragma unroll
    for (int cls = 0; cls < 3; cls++) {
        float s = 0.0f;
        for (int c = lane; c < 256; c += 32) s += f1[c] * wh1[cls * 256 + c];
#pragma unroll
        for (int off = 16; off > 0; off >>= 1) s += __shfl_xor_sync(0xffffffffu, s, off);
        lg1[cls] = s * inv_pool + bh1[cls];
    }
#pragma unroll
    for (int cls = 0; cls < 2; cls++) {
        float s = 0.0f;
        for (int c = lane; c < 256; c += 32) s += f2[c] * wh2[cls * 256 + c];
#pragma unroll
        for (int off = 16; off > 0; off >>= 1) s += __shfl_xor_sync(0xffffffffu, s, off);
        lg2[cls] = s * inv_pool + bh2[cls];
    }

    if (lane == 0) {
        float m = fmaxf(lg1[0], fmaxf(lg1[1], lg1[2]));
        float e0 = expf(lg1[0] - m), e1 = expf(lg1[1] - m), e2 = expf(lg1[2] - m);
        float inv = 1.0f / (e0 + e1 + e2);
        float p0 = e0 * inv, p1 = e1 * inv, p2 = e2 * inv;
        int pred = 0; float best = p0;
        if (p1 > best) { best = p1; pred = 1; }
        if (p2 > best) { best = p2; pred = 2; }

        float m2 = fmaxf(lg2[0], lg2[1]);
        float q0 = expf(lg2[0] - m2), q1 = expf(lg2[1] - m2);
        float inv2 = 1.0f / (q0 + q1);
        q0 *= inv2; q1 *= inv2;

        out[b * 4 + 0] = (pred == 0) ? p0 : 0.0f;
        out[b * 4 + 1] = (pred == 1) ? p1 : 0.0f;
        out[b * 4 + 2] = (pred == 2) ? q0 : 0.0f;
        out[b * 4 + 3] = (pred == 2) ? q1 : 0.0f;
    }
}

// ---------------------------------------------------------------------------
extern "C" void kernel_launch(void* const* d_in, const int* in_sizes, int n_in,
                              void* d_out, int out_size)
{
    (void)in_sizes; (void)n_in; (void)out_size;
    const float* x = (const float*)d_in[0];

    const float* W[2][8];
    for (int net = 0; net < 2; net++)
        for (int i = 0; i < 8; i++)
            W[net][i] = (const float*)d_in[1 + net * 8 + i];

    float* out = (float*)d_out;

    float* feat;
    cudaGetSymbolAddress((void**)&feat, g_feat);

    cudaFuncSetAttribute(conv01_mma_kernel,
                         cudaFuncAttributeMaxDynamicSharedMemorySize, C1_SMEM);
    cudaFuncSetAttribute(conv2_mma_kernel,
                         cudaFuncAttributeMaxDynamicSharedMemorySize, C2_SMEM);

    zero_feat_kernel<<<1024, 256>>>();
    prep_w1_kernel<<<320, 256>>>(W[0][2], W[1][2]);
    prep_w2_kernel<<<1280, 256>>>(W[0][4], W[1][4]);

    for (int net = 0; net < 2; net++) {
        conv0_kernel<<<dim3(512, 32), 256>>>(x, W[net][0], W[net][1]);
        conv01_mma_kernel<<<dim3(512, 8), 256, C1_SMEM>>>(W[net][3], net);
        conv2_mma_kernel<<<dim3(512, 4, 2), 256, C2_SMEM>>>(
            W[net][5], feat + (size_t)net * 512 * 256, net);
    }

    head_kernel<<<512, 32>>>(W[0][6], W[0][7], W[1][6], W[1][7], out);
}